// round 4
// baseline (speedup 1.0000x reference)
#include <cuda_runtime.h>
#include <cuda_bf16.h>
#include <cstdint>

// ---------------- problem constants (fixed by registry) ----------------
constexpr int T_  = 4096;   // B*S tokens
constexpr int D_  = 1024;   // model dim
constexpr int H_  = 4096;   // hidden dim
constexpr int E_  = 8;      // experts
constexpr int TOPK = 2;

// GEMM tiling
constexpr int TM = 128, TN = 128, TKK = 16;
constexpr int RP = 9216;          // padded assignment rows cap: 8192 + 8*128
constexpr int NT = RP / TM;       // 72 row tiles

// ---------------- device-global scratch (no allocations allowed) -------
__device__ int   g_top_i[2 * T_];
__device__ float g_top_w[2 * T_];
__device__ float g_probs[T_ * E_];
__device__ float g_probsum[E_];
__device__ int   g_cnt[E_];
__device__ int   g_cursor[E_];
__device__ int   g_aoff[E_ + 1];
__device__ int   g_tile_expert[NT];
__device__ int   g_assign_token[RP];
__device__ float g_assign_w[RP];
__device__ int   g_token_slot[2 * T_];
__device__ float g_h[(size_t)RP * H_];   // ~151 MB intermediate
__device__ float g_y[(size_t)RP * D_];   // ~38 MB per-assignment outputs

// ---------------- reset (graph replays must be idempotent) -------------
__global__ void k_reset() {
    int i = blockIdx.x * blockDim.x + threadIdx.x;
    if (i < RP) { g_assign_token[i] = -1; g_assign_w[i] = 0.f; }
    if (i < E_) g_cnt[i] = 0;
}

// ---------------- router: logits, softmax, top-2, counts ---------------
__global__ void k_router(const float* __restrict__ x, const float* __restrict__ Wg) {
    int t = blockIdx.x;
    int lane = threadIdx.x & 31, w = threadIdx.x >> 5;   // 8 warps, one per expert
    const float* xt = x + (size_t)t * D_;
    const float* wg = Wg + (size_t)w * D_;
    float s = 0.f;
    #pragma unroll 8
    for (int j = lane; j < D_; j += 32) s += xt[j] * wg[j];
    #pragma unroll
    for (int o = 16; o; o >>= 1) s += __shfl_xor_sync(0xffffffffu, s, o);
    __shared__ float sl[E_];
    if (lane == 0) sl[w] = s;
    __syncthreads();
    if (threadIdx.x == 0) {
        float mx = sl[0];
        #pragma unroll
        for (int e = 1; e < E_; e++) mx = fmaxf(mx, sl[e]);
        float p[E_], sum = 0.f;
        #pragma unroll
        for (int e = 0; e < E_; e++) { p[e] = __expf(sl[e] - mx); sum += p[e]; }
        float inv = 1.f / sum;
        #pragma unroll
        for (int e = 0; e < E_; e++) { p[e] *= inv; g_probs[t * E_ + e] = p[e]; }
        int i0 = 0;
        #pragma unroll
        for (int e = 1; e < E_; e++) if (p[e] > p[i0]) i0 = e;
        int i1 = -1;
        #pragma unroll
        for (int e = 0; e < E_; e++) {
            if (e == i0) continue;
            if (i1 < 0 || p[e] > p[i1]) i1 = e;
        }
        float v0 = p[i0], v1 = p[i1], s2 = v0 + v1;
        g_top_i[2 * t] = i0;  g_top_i[2 * t + 1] = i1;
        g_top_w[2 * t] = v0 / s2;  g_top_w[2 * t + 1] = v1 / s2;
        atomicAdd(&g_cnt[i0], 1);
        atomicAdd(&g_cnt[i1], 1);
    }
}

// ---------------- deterministic mean-prob reduction --------------------
__global__ void k_probs_reduce() {
    int e = blockIdx.x, tid = threadIdx.x;
    float s = 0.f;
    for (int t = tid; t < T_; t += 256) s += g_probs[t * E_ + e];
    __shared__ float red[256];
    red[tid] = s; __syncthreads();
    for (int o = 128; o; o >>= 1) { if (tid < o) red[tid] += red[tid + o]; __syncthreads(); }
    if (tid == 0) g_probsum[e] = red[0];
}

// ---------------- plan: 128-aligned expert segments + tile map ---------
__global__ void k_plan() {
    if (threadIdx.x == 0) {
        int off = 0;
        for (int e = 0; e < E_; e++) {
            g_aoff[e] = off;
            int c = g_cnt[e];
            int tiles = (c + TM - 1) / TM;
            int bt = off / TM;
            for (int tt = 0; tt < tiles; tt++) g_tile_expert[bt + tt] = e;
            off += tiles * TM;
            g_cursor[e] = 0;
        }
        g_aoff[E_] = off;
        for (int m = off / TM; m < NT; m++) g_tile_expert[m] = -1;
    }
}

// ---------------- scatter tokens into expert segments ------------------
__global__ void k_scatter() {
    int t = blockIdx.x * blockDim.x + threadIdx.x;
    if (t >= T_) return;
    #pragma unroll
    for (int k = 0; k < TOPK; k++) {
        int e = g_top_i[2 * t + k];
        int pos = atomicAdd(&g_cursor[e], 1);
        int slot = g_aoff[e] + pos;
        g_assign_token[slot] = t;
        g_assign_w[slot] = g_top_w[2 * t + k];
        g_token_slot[2 * t + k] = slot;
    }
}

// ---------------- GEMM1: h = silu(gather(x) @ W1[e] + b1[e]) -----------
__global__ __launch_bounds__(256, 2)
void k_gemm1(const float* __restrict__ x, const float* __restrict__ W1,
             const float* __restrict__ b1) {
    int mt = blockIdx.y, nt = blockIdx.x;
    int e = g_tile_expert[mt];
    if (e < 0) return;
    __shared__ float As[TKK][TM];
    __shared__ float Bs[TKK][TN];
    __shared__ int s_tok[TM];
    int tid = threadIdx.x;
    int row0 = mt * TM;
    if (tid < TM) s_tok[tid] = g_assign_token[row0 + tid];
    __syncthreads();
    const float* Bptr = W1 + (size_t)e * D_ * H_ + nt * TN;
    float acc[8][8] = {};
    int tx = tid & 15, ty = tid >> 4;
    for (int k0 = 0; k0 < D_; k0 += TKK) {
        #pragma unroll
        for (int q = tid; q < 512; q += 256) {      // A: 128x16 (gathered)
            int r = q >> 2, kv = q & 3;
            int tok = s_tok[r];
            float4 v = make_float4(0.f, 0.f, 0.f, 0.f);
            if (tok >= 0)
                v = *(const float4*)(x + (size_t)tok * D_ + k0 + kv * 4);
            As[kv * 4 + 0][r] = v.x; As[kv * 4 + 1][r] = v.y;
            As[kv * 4 + 2][r] = v.z; As[kv * 4 + 3][r] = v.w;
        }
        #pragma unroll
        for (int q = tid; q < 512; q += 256) {      // B: 16x128
            int kr = q >> 5, nv = q & 31;
            *(float4*)&Bs[kr][nv * 4] =
                *(const float4*)(Bptr + (size_t)(k0 + kr) * H_ + nv * 4);
        }
        __syncthreads();
        #pragma unroll
        for (int k = 0; k < TKK; ++k) {
            float a[8], b[8];
            *(float4*)(a)     = *(float4*)&As[k][ty * 8];
            *(float4*)(a + 4) = *(float4*)&As[k][ty * 8 + 4];
            *(float4*)(b)     = *(float4*)&Bs[k][tx * 8];
            *(float4*)(b + 4) = *(float4*)&Bs[k][tx * 8 + 4];
            #pragma unroll
            for (int i = 0; i < 8; i++)
                #pragma unroll
                for (int j = 0; j < 8; j++) acc[i][j] += a[i] * b[j];
        }
        __syncthreads();
    }
    int col0 = nt * TN + tx * 8;
    const float* b1e = b1 + (size_t)e * H_;
    float bv[8];
    #pragma unroll
    for (int j = 0; j < 8; j++) bv[j] = b1e[col0 + j];
    #pragma unroll
    for (int i = 0; i < 8; i++) {
        int grow = row0 + ty * 8 + i;
        float o[8];
        #pragma unroll
        for (int j = 0; j < 8; j++) {
            float v = acc[i][j] + bv[j];
            o[j] = v * __fdividef(1.f, 1.f + __expf(-v));   // silu
        }
        float* hp = g_h + (size_t)grow * H_ + col0;
        *(float4*)hp       = *(float4*)o;
        *(float4*)(hp + 4) = *(float4*)(o + 4);
    }
}

// ---------------- GEMM2: y = h @ W2[e] + b2[e] -------------------------
__global__ __launch_bounds__(256, 2)
void k_gemm2(const float* __restrict__ W2, const float* __restrict__ b2) {
    int mt = blockIdx.y, nt = blockIdx.x;
    int e = g_tile_expert[mt];
    if (e < 0) return;
    __shared__ float As[TKK][TM];
    __shared__ float Bs[TKK][TN];
    int tid = threadIdx.x;
    int row0 = mt * TM;
    const float* Bptr = W2 + (size_t)e * H_ * D_ + nt * TN;
    float acc[8][8] = {};
    int tx = tid & 15, ty = tid >> 4;
    for (int k0 = 0; k0 < H_; k0 += TKK) {
        #pragma unroll
        for (int q = tid; q < 512; q += 256) {      // A: 128x16 from g_h
            int r = q >> 2, kv = q & 3;
            float4 v = *(const float4*)(g_h + (size_t)(row0 + r) * H_ + k0 + kv * 4);
            As[kv * 4 + 0][r] = v.x; As[kv * 4 + 1][r] = v.y;
            As[kv * 4 + 2][r] = v.z; As[kv * 4 + 3][r] = v.w;
        }
        #pragma unroll
        for (int q = tid; q < 512; q += 256) {      // B: 16x128
            int kr = q >> 5, nv = q & 31;
            *(float4*)&Bs[kr][nv * 4] =
                *(const float4*)(Bptr + (size_t)(k0 + kr) * D_ + nv * 4);
        }
        __syncthreads();
        #pragma unroll
        for (int k = 0; k < TKK; ++k) {
            float a[8], b[8];
            *(float4*)(a)     = *(float4*)&As[k][ty * 8];
            *(float4*)(a + 4) = *(float4*)&As[k][ty * 8 + 4];
            *(float4*)(b)     = *(float4*)&Bs[k][tx * 8];
            *(float4*)(b + 4) = *(float4*)&Bs[k][tx * 8 + 4];
            #pragma unroll
            for (int i = 0; i < 8; i++)
                #pragma unroll
                for (int j = 0; j < 8; j++) acc[i][j] += a[i] * b[j];
        }
        __syncthreads();
    }
    int col0 = nt * TN + tx * 8;
    const float* b2e = b2 + (size_t)e * D_;
    float bv[8];
    #pragma unroll
    for (int j = 0; j < 8; j++) bv[j] = b2e[col0 + j];
    #pragma unroll
    for (int i = 0; i < 8; i++) {
        int grow = row0 + ty * 8 + i;
        float o[8];
        #pragma unroll
        for (int j = 0; j < 8; j++) o[j] = acc[i][j] + bv[j];
        float* yp = g_y + (size_t)grow * D_ + col0;
        *(float4*)yp       = *(float4*)o;
        *(float4*)(yp + 4) = *(float4*)(o + 4);
    }
}

// ---------------- combine: out[t] = w0*y[slot0] + w1*y[slot1] ----------
__global__ void k_combine(float* __restrict__ out) {
    int idx = blockIdx.x * 256 + threadIdx.x;     // over T*D/4 float4s
    if (idx >= T_ * D_ / 4) return;
    int t = idx / (D_ / 4);
    int v = idx % (D_ / 4);
    int s0 = g_token_slot[2 * t], s1 = g_token_slot[2 * t + 1];
    float w0 = g_assign_w[s0], w1 = g_assign_w[s1];
    float4 y0 = *(const float4*)(g_y + (size_t)s0 * D_ + v * 4);
    float4 y1 = *(const float4*)(g_y + (size_t)s1 * D_ + v * 4);
    float4 o;
    o.x = w0 * y0.x + w1 * y1.x;
    o.y = w0 * y0.y + w1 * y1.y;
    o.z = w0 * y0.z + w1 * y1.z;
    o.w = w0 * y0.w + w1 * y1.w;
    *(float4*)(out + (size_t)t * D_ + v * 4) = o;
}

// ---------------- aux loss scalar --------------------------------------
__global__ void k_aux(float* __restrict__ out, int out_size) {
    if (threadIdx.x == 0 && out_size > T_ * D_) {
        float a = 0.f;
        #pragma unroll
        for (int e = 0; e < E_; e++)
            a += ((float)g_cnt[e] / (float)T_) * (g_probsum[e] / (float)T_);
        out[(size_t)T_ * D_] = (float)E_ * a;
    }
}

// ---------------- launch ------------------------------------------------
extern "C" void kernel_launch(void* const* d_in, const int* in_sizes, int n_in,
                              void* d_out, int out_size) {
    const float* x  = (const float*)d_in[0];
    const float* Wg = (const float*)d_in[1];
    const float* W1 = (const float*)d_in[2];
    const float* b1 = (const float*)d_in[3];
    const float* W2 = (const float*)d_in[4];
    const float* b2 = (const float*)d_in[5];
    float* out = (float*)d_out;
    (void)in_sizes; (void)n_in;

    k_reset<<<(RP + 255) / 256, 256>>>();
    k_router<<<T_, 256>>>(x, Wg);
    k_probs_reduce<<<E_, 256>>>();
    k_plan<<<1, 32>>>();
    k_scatter<<<(T_ + 255) / 256, 256>>>();
    k_gemm1<<<dim3(H_ / TN, NT), 256>>>(x, W1, b1);
    k_gemm2<<<dim3(D_ / TN, NT), 256>>>(W2, b2);
    k_combine<<<(T_ * D_ / 4 + 255) / 256, 256>>>(out);
    k_aux<<<1, 32>>>(out, out_size);
}

// round 12
// speedup vs baseline: 2.1744x; 2.1744x over previous
#include <cuda_runtime.h>
#include <cuda_bf16.h>
#include <cstdint>

// ---------------- problem constants ----------------
constexpr int T_  = 4096;
constexpr int D_  = 1024;
constexpr int H_  = 4096;
constexpr int E_  = 8;
constexpr int TOPK = 2;

constexpr int TM = 128;
constexpr int RP = 9216;
constexpr int NT = RP / TM;      // 72 row tiles

// mma GEMM tiling
constexpr int KC  = 32;          // K elems per chunk
constexpr int RSB = 80;          // smem row stride bytes (64B data + 16B pad)
constexpr int PL  = 128 * RSB;   // 10240 B per plane (128 rows)
constexpr int STG = 4 * PL;      // Ah, Al, Bh, Bl per stage = 40960 B
constexpr int SMEM_SZ = 1024 + 2 * STG;   // 82944 B

// ---------------- device-global scratch (256B-aligned: cp.async-safe) ----
__device__ __align__(256) int   g_top_i[2 * T_];
__device__ __align__(256) float g_top_w[2 * T_];
__device__ __align__(256) float g_probs[T_ * E_];
__device__ __align__(256) float g_probsum[E_];
__device__ __align__(256) int   g_cnt[E_];
__device__ __align__(256) int   g_cursor[E_];
__device__ __align__(256) int   g_aoff[E_ + 1];
__device__ __align__(256) int   g_tile_expert[NT];
__device__ __align__(256) int   g_assign_token[RP];
__device__ __align__(256) float g_assign_w[RP];
__device__ __align__(256) int   g_token_slot[2 * T_];

__device__ __align__(256) __nv_bfloat16 g_xh[T_ * D_];
__device__ __align__(256) __nv_bfloat16 g_xl[T_ * D_];
__device__ __align__(256) __nv_bfloat16 g_w1h[E_ * H_ * D_];  // W1^T: [E][H][D] K-major
__device__ __align__(256) __nv_bfloat16 g_w1l[E_ * H_ * D_];
__device__ __align__(256) __nv_bfloat16 g_w2h[E_ * D_ * H_];  // W2^T: [E][D][H] K-major
__device__ __align__(256) __nv_bfloat16 g_w2l[E_ * D_ * H_];
__device__ __align__(256) __nv_bfloat16 g_hh[RP * H_];
__device__ __align__(256) __nv_bfloat16 g_hl[RP * H_];
__device__ __align__(256) float g_y[(size_t)RP * D_];

// ---------------- PTX helpers (baseline PTX only) ----------------
__device__ __forceinline__ uint32_t smem_u32(const void* p) {
    return (uint32_t)__cvta_generic_to_shared(p);
}
__device__ __forceinline__ void cpa16(uint32_t s, const void* g) {
    asm volatile("cp.async.cg.shared.global [%0], [%1], 16;\n" :: "r"(s), "l"(g));
}
__device__ __forceinline__ void cpa_commit() {
    asm volatile("cp.async.commit_group;\n" ::: "memory");
}
__device__ __forceinline__ void mma_bf16(float* d, const uint32_t* a, const uint32_t* b) {
    asm volatile(
        "mma.sync.aligned.m16n8k16.row.col.f32.bf16.bf16.f32 "
        "{%0,%1,%2,%3}, {%4,%5,%6,%7}, {%8,%9}, {%0,%1,%2,%3};"
        : "+f"(d[0]), "+f"(d[1]), "+f"(d[2]), "+f"(d[3])
        : "r"(a[0]), "r"(a[1]), "r"(a[2]), "r"(a[3]), "r"(b[0]), "r"(b[1]));
}

// ---------------- reset ----------------
__global__ void k_reset() {
    int i = blockIdx.x * blockDim.x + threadIdx.x;
    if (i < RP) { g_assign_token[i] = -1; g_assign_w[i] = 0.f; }
    if (i < E_) g_cnt[i] = 0;
}

// ---------------- router ----------------
__global__ void k_router(const float* __restrict__ x, const float* __restrict__ Wg) {
    int t = blockIdx.x;
    int lane = threadIdx.x & 31, w = threadIdx.x >> 5;
    const float* xt = x + (size_t)t * D_;
    const float* wg = Wg + (size_t)w * D_;
    float s = 0.f;
    #pragma unroll 8
    for (int j = lane; j < D_; j += 32) s += xt[j] * wg[j];
    #pragma unroll
    for (int o = 16; o; o >>= 1) s += __shfl_xor_sync(0xffffffffu, s, o);
    __shared__ float sl[E_];
    if (lane == 0) sl[w] = s;
    __syncthreads();
    if (threadIdx.x == 0) {
        float mx = sl[0];
        #pragma unroll
        for (int e = 1; e < E_; e++) mx = fmaxf(mx, sl[e]);
        float p[E_], sum = 0.f;
        #pragma unroll
        for (int e = 0; e < E_; e++) { p[e] = __expf(sl[e] - mx); sum += p[e]; }
        float inv = 1.f / sum;
        #pragma unroll
        for (int e = 0; e < E_; e++) { p[e] *= inv; g_probs[t * E_ + e] = p[e]; }
        int i0 = 0;
        #pragma unroll
        for (int e = 1; e < E_; e++) if (p[e] > p[i0]) i0 = e;
        int i1 = -1;
        #pragma unroll
        for (int e = 0; e < E_; e++) {
            if (e == i0) continue;
            if (i1 < 0 || p[e] > p[i1]) i1 = e;
        }
        float v0 = p[i0], v1 = p[i1], s2 = v0 + v1;
        g_top_i[2 * t] = i0;  g_top_i[2 * t + 1] = i1;
        g_top_w[2 * t] = v0 / s2;  g_top_w[2 * t + 1] = v1 / s2;
        atomicAdd(&g_cnt[i0], 1);
        atomicAdd(&g_cnt[i1], 1);
    }
}

__global__ void k_probs_reduce() {
    int e = blockIdx.x, tid = threadIdx.x;
    float s = 0.f;
    for (int t = tid; t < T_; t += 256) s += g_probs[t * E_ + e];
    __shared__ float red[256];
    red[tid] = s; __syncthreads();
    for (int o = 128; o; o >>= 1) { if (tid < o) red[tid] += red[tid + o]; __syncthreads(); }
    if (tid == 0) g_probsum[e] = red[0];
}

__global__ void k_plan() {
    if (threadIdx.x == 0) {
        int off = 0;
        for (int e = 0; e < E_; e++) {
            g_aoff[e] = off;
            int c = g_cnt[e];
            int tiles = (c + TM - 1) / TM;
            int bt = off / TM;
            for (int tt = 0; tt < tiles; tt++) g_tile_expert[bt + tt] = e;
            off += tiles * TM;
            g_cursor[e] = 0;
        }
        g_aoff[E_] = off;
        for (int m = off / TM; m < NT; m++) g_tile_expert[m] = -1;
    }
}

__global__ void k_scatter() {
    int t = blockIdx.x * blockDim.x + threadIdx.x;
    if (t >= T_) return;
    #pragma unroll
    for (int k = 0; k < TOPK; k++) {
        int e = g_top_i[2 * t + k];
        int pos = atomicAdd(&g_cursor[e], 1);
        int slot = g_aoff[e] + pos;
        g_assign_token[slot] = t;
        g_assign_w[slot] = g_top_w[2 * t + k];
        g_token_slot[2 * t + k] = slot;
    }
}

// ---------------- prep: fp32 -> bf16 hi/lo planes ----------------
__global__ void k_cvt_x(const float* __restrict__ x) {
    int i = blockIdx.x * 256 + threadIdx.x;
    if (i < T_ * D_) {
        float v = x[i];
        __nv_bfloat16 h = __float2bfloat16(v);
        g_xh[i] = h;
        g_xl[i] = __float2bfloat16(v - __bfloat162float(h));
    }
}

// transpose + split: W [E][R][Cc] -> global planes [E][Cc][R] (bf16 hi/lo).
// NOTE: destination __device__ symbols are selected INSIDE device code —
// passing them as host-side kernel args resolves the host shadow address
// (and on GB300's ATS that write silently lands in host memory).
template<bool W1SEL>
__global__ void k_tr(const float* __restrict__ W) {
    constexpr int R  = W1SEL ? D_ : H_;   // input rows  (contraction dim)
    constexpr int Cc = W1SEL ? H_ : D_;   // input cols  (output-major dim)
    __nv_bfloat16* Oh = W1SEL ? g_w1h : g_w2h;
    __nv_bfloat16* Ol = W1SEL ? g_w1l : g_w2l;
    __shared__ float t[32][33];
    int ez = blockIdx.z;
    const float* We = W + (size_t)ez * R * Cc;
    int c0 = blockIdx.x * 32, r0 = blockIdx.y * 32;
    int tx = threadIdx.x, ty = threadIdx.y;
    #pragma unroll
    for (int i = ty; i < 32; i += 8)
        t[i][tx] = We[(size_t)(r0 + i) * Cc + c0 + tx];
    __syncthreads();
    __nv_bfloat16* OhE = Oh + (size_t)ez * R * Cc;
    __nv_bfloat16* OlE = Ol + (size_t)ez * R * Cc;
    #pragma unroll
    for (int i = ty; i < 32; i += 8) {
        float v = t[tx][i];
        __nv_bfloat16 h = __float2bfloat16(v);
        size_t o = (size_t)(c0 + i) * R + r0 + tx;
        OhE[o] = h;
        OlE[o] = __float2bfloat16(v - __bfloat162float(h));
    }
}

// ---------------- grouped GEMM via mma.sync (bf16 hi/lo split) ----------------
// CTA 128x128, KC=32 double-buffered cp.async, 8 warps of 32x64.
// Fragments loaded with direct per-thread LDS.32 from documented mma coords:
//   A[m][k] row-major in smem; B[n][k] (n rows, k contiguous).
template<bool G1>
__global__ __launch_bounds__(256) void k_gemm_mma(const float* __restrict__ bias_all) {
    int mt = blockIdx.y, nb = blockIdx.x;
    int e = g_tile_expert[mt];
    if (e < 0) return;
    extern __shared__ char smem[];
    float* s_bias = (float*)smem;
    int*   s_tok  = (int*)(smem + 512);
    char*  sdata  = smem + 1024;                 // stage data (generic ptr for LDS)
    uint32_t sb32 = smem_u32(smem) + 1024;       // .shared addr for cp.async
    constexpr int KD  = G1 ? D_ : H_;
    constexpr int NBW = G1 ? H_ : D_;
    constexpr int C   = KD / KC;
    int tid = threadIdx.x, lane = tid & 31, wid = tid >> 5;
    int row0 = mt * TM;

    if (tid < 128) s_bias[tid] = bias_all[(size_t)e * NBW + nb * 128 + tid];
    if (G1 && tid < 128) { int tk = g_assign_token[row0 + tid]; s_tok[tid] = tk < 0 ? 0 : tk; }
    __syncthreads();

    const __nv_bfloat16 *Ah, *Al, *Bh, *Bl;
    if (G1) { Ah = g_xh; Al = g_xl; Bh = g_w1h; Bl = g_w1l; }
    else    { Ah = g_hh; Al = g_hl; Bh = g_w2h; Bl = g_w2l; }
    size_t bbase = (size_t)e * (size_t)H_ * D_ + (size_t)(nb * 128) * KD;

    auto load_chunk = [&](int c, int s) {
        uint32_t st = sb32 + s * STG;
        int k0 = c * KC;
        #pragma unroll
        for (int q = tid; q < 512; q += 256) {           // A hi/lo: 128 rows x 64B
            int r = q >> 2, cc = q & 3;
            size_t go = (G1 ? (size_t)s_tok[r] * D_ : (size_t)(row0 + r) * H_) + k0 + cc * 8;
            uint32_t so = (uint32_t)(r * RSB + cc * 16);
            cpa16(st + so, Ah + go);
            cpa16(st + PL + so, Al + go);
        }
        #pragma unroll
        for (int q = tid; q < 512; q += 256) {           // B hi/lo: 128 rows x 64B
            int r = q >> 2, cc = q & 3;
            size_t go = bbase + (size_t)r * KD + k0 + cc * 8;
            uint32_t so = (uint32_t)(r * RSB + cc * 16);
            cpa16(st + 2 * PL + so, Bh + go);
            cpa16(st + 3 * PL + so, Bl + go);
        }
        cpa_commit();
    };

    int wm = (wid & 3) * 32, wn = (wid >> 2) * 64;
    int g = lane >> 2, tig = lane & 3;
    // per-thread fragment byte offsets within a plane (add ko for k-step)
    uint32_t aF = (uint32_t)((wm + g) * RSB + tig * 4);
    uint32_t bF = (uint32_t)((wn + g) * RSB + tig * 4);

    float acc[2][8][4] = {};
    load_chunk(0, 0);
    for (int c = 0; c < C; ++c) {
        int s = c & 1;
        if (c + 1 < C) {
            load_chunk(c + 1, s ^ 1);
            asm volatile("cp.async.wait_group 1;\n" ::: "memory");
        } else {
            asm volatile("cp.async.wait_group 0;\n" ::: "memory");
        }
        __syncthreads();
        char* pAh = sdata + s * STG;
        char* pAl = pAh + PL;
        char* pBh = pAh + 2 * PL;
        char* pBl = pAh + 3 * PL;
        #pragma unroll
        for (int ks = 0; ks < 2; ks++) {
            uint32_t ko = ks * 32;
            uint32_t am[8], bx[16];
            // --- hi(A) fragments: 2 m-tiles x {a0,a1,a2,a3} ---
            #pragma unroll
            for (int m = 0; m < 2; m++) {
                uint32_t base = aF + m * 16 * RSB + ko;
                am[4 * m + 0] = *(const uint32_t*)(pAh + base);
                am[4 * m + 1] = *(const uint32_t*)(pAh + base + 8 * RSB);
                am[4 * m + 2] = *(const uint32_t*)(pAh + base + 16);
                am[4 * m + 3] = *(const uint32_t*)(pAh + base + 8 * RSB + 16);
            }
            // --- hi(B) fragments: 8 n-blocks x {b0,b1} ---
            #pragma unroll
            for (int n = 0; n < 8; n++) {
                uint32_t base = bF + n * 8 * RSB + ko;
                bx[2 * n + 0] = *(const uint32_t*)(pBh + base);
                bx[2 * n + 1] = *(const uint32_t*)(pBh + base + 16);
            }
            #pragma unroll
            for (int m = 0; m < 2; m++)
                #pragma unroll
                for (int n = 0; n < 8; n++)
                    mma_bf16(acc[m][n], am + 4 * m, bx + 2 * n);     // hi*hi
            {   // lo(A) * hi(B)
                uint32_t al[8];
                #pragma unroll
                for (int m = 0; m < 2; m++) {
                    uint32_t base = aF + m * 16 * RSB + ko;
                    al[4 * m + 0] = *(const uint32_t*)(pAl + base);
                    al[4 * m + 1] = *(const uint32_t*)(pAl + base + 8 * RSB);
                    al[4 * m + 2] = *(const uint32_t*)(pAl + base + 16);
                    al[4 * m + 3] = *(const uint32_t*)(pAl + base + 8 * RSB + 16);
                }
                #pragma unroll
                for (int m = 0; m < 2; m++)
                    #pragma unroll
                    for (int n = 0; n < 8; n++)
                        mma_bf16(acc[m][n], al + 4 * m, bx + 2 * n);
            }
            {   // hi(A) * lo(B)
                #pragma unroll
                for (int n = 0; n < 8; n++) {
                    uint32_t base = bF + n * 8 * RSB + ko;
                    bx[2 * n + 0] = *(const uint32_t*)(pBl + base);
                    bx[2 * n + 1] = *(const uint32_t*)(pBl + base + 16);
                }
                #pragma unroll
                for (int m = 0; m < 2; m++)
                    #pragma unroll
                    for (int n = 0; n < 8; n++)
                        mma_bf16(acc[m][n], am + 4 * m, bx + 2 * n);
            }
        }
        __syncthreads();
    }

    // ---- epilogue ----
    int rbase = row0 + wm + g;
    int cloc0 = wn + tig * 2;
    #pragma unroll
    for (int m = 0; m < 2; m++) {
        #pragma unroll
        for (int n = 0; n < 8; n++) {
            int cl = cloc0 + n * 8;
            int gc = nb * 128 + cl;
            float b0 = s_bias[cl], b1 = s_bias[cl + 1];
            #pragma unroll
            for (int hrow = 0; hrow < 2; hrow++) {
                int gr = rbase + m * 16 + hrow * 8;
                float v0 = acc[m][n][2 * hrow + 0] + b0;
                float v1 = acc[m][n][2 * hrow + 1] + b1;
                if (G1) {
                    float s0 = v0 * __fdividef(1.f, 1.f + __expf(-v0));
                    float s1 = v1 * __fdividef(1.f, 1.f + __expf(-v1));
                    __nv_bfloat16 h0 = __float2bfloat16(s0), h1 = __float2bfloat16(s1);
                    __nv_bfloat162 hp; hp.x = h0; hp.y = h1;
                    __nv_bfloat162 lp;
                    lp.x = __float2bfloat16(s0 - __bfloat162float(h0));
                    lp.y = __float2bfloat16(s1 - __bfloat162float(h1));
                    size_t o = (size_t)gr * H_ + gc;
                    *(__nv_bfloat162*)(g_hh + o) = hp;
                    *(__nv_bfloat162*)(g_hl + o) = lp;
                } else {
                    size_t o = (size_t)gr * D_ + gc;
                    float2 fv; fv.x = v0; fv.y = v1;
                    *(float2*)(g_y + o) = fv;
                }
            }
        }
    }
}

// ---------------- combine + aux ----------------
__global__ void k_combine(float* __restrict__ out) {
    int idx = blockIdx.x * 256 + threadIdx.x;
    if (idx >= T_ * D_ / 4) return;
    int t = idx / (D_ / 4);
    int v = idx % (D_ / 4);
    int s0 = g_token_slot[2 * t], s1 = g_token_slot[2 * t + 1];
    float w0 = g_assign_w[s0], w1 = g_assign_w[s1];
    float4 y0 = *(const float4*)(g_y + (size_t)s0 * D_ + v * 4);
    float4 y1 = *(const float4*)(g_y + (size_t)s1 * D_ + v * 4);
    float4 o;
    o.x = w0 * y0.x + w1 * y1.x;
    o.y = w0 * y0.y + w1 * y1.y;
    o.z = w0 * y0.z + w1 * y1.z;
    o.w = w0 * y0.w + w1 * y1.w;
    *(float4*)(out + (size_t)t * D_ + v * 4) = o;
}

__global__ void k_aux(float* __restrict__ out, int out_size) {
    if (threadIdx.x == 0 && out_size > T_ * D_) {
        float a = 0.f;
        #pragma unroll
        for (int e = 0; e < E_; e++)
            a += ((float)g_cnt[e] / (float)T_) * (g_probsum[e] / (float)T_);
        out[(size_t)T_ * D_] = (float)E_ * a;
    }
}

// ---------------- launch ----------------
extern "C" void kernel_launch(void* const* d_in, const int* in_sizes, int n_in,
                              void* d_out, int out_size) {
    const float* x  = (const float*)d_in[0];
    const float* Wg = (const float*)d_in[1];
    const float* W1 = (const float*)d_in[2];
    const float* b1 = (const float*)d_in[3];
    const float* W2 = (const float*)d_in[4];
    const float* b2 = (const float*)d_in[5];
    float* out = (float*)d_out;
    (void)in_sizes; (void)n_in;

    cudaFuncSetAttribute(k_gemm_mma<true>,
                         cudaFuncAttributeMaxDynamicSharedMemorySize, SMEM_SZ);
    cudaFuncSetAttribute(k_gemm_mma<false>,
                         cudaFuncAttributeMaxDynamicSharedMemorySize, SMEM_SZ);

    k_reset<<<(RP + 255) / 256, 256>>>();
    k_router<<<T_, 256>>>(x, Wg);
    k_probs_reduce<<<E_, 256>>>();
    k_plan<<<1, 32>>>();
    k_scatter<<<(T_ + 255) / 256, 256>>>();

    // prep: fp32 -> bf16 hi/lo planes, weights transposed K-major
    k_cvt_x<<<(T_ * D_ + 255) / 256, 256>>>(x);
    k_tr<true ><<<dim3(H_ / 32, D_ / 32, E_), dim3(32, 8)>>>(W1);
    k_tr<false><<<dim3(D_ / 32, H_ / 32, E_), dim3(32, 8)>>>(W2);

    k_gemm_mma<true ><<<dim3(H_ / 128, NT), 256, SMEM_SZ>>>(b1);
    k_gemm_mma<false><<<dim3(D_ / 128, NT), 256, SMEM_SZ>>>(b2);

    k_combine<<<(T_ * D_ / 4 + 255) / 256, 256>>>(out);
    k_aux<<<1, 32>>>(out, out_size);
}

// round 13
// speedup vs baseline: 2.5541x; 1.1746x over previous
#include <cuda_runtime.h>
#include <cuda_fp16.h>
#include <cstdint>

// ---------------- problem constants ----------------
constexpr int T_  = 4096;
constexpr int D_  = 1024;
constexpr int H_  = 4096;
constexpr int E_  = 8;
constexpr int TOPK = 2;

constexpr int TM = 128;
constexpr int RP = 9216;
constexpr int NT = RP / TM;      // 72 row tiles

// mma GEMM tiling
constexpr int KC  = 32;          // K elems per chunk
constexpr int RSB = 80;          // smem row stride bytes (64B data + 16B pad)
constexpr int PL  = 128 * RSB;   // 10240 B per plane (128 rows)
constexpr int SMEM1 = 1024 + 2 * 4 * PL;   // G1: Ah,Al,Bh,Bl x2 stages = 82944
constexpr int SMEM2 = 1024 + 2 * 3 * PL;   // G2: A,Bh,Bl x2 stages  = 62464

// ---------------- device-global scratch (256B-aligned: cp.async-safe) ----
__device__ __align__(256) int   g_top_i[2 * T_];
__device__ __align__(256) float g_top_w[2 * T_];
__device__ __align__(256) float g_probs[T_ * E_];
__device__ __align__(256) float g_probsum[E_];
__device__ __align__(256) int   g_cnt[E_];
__device__ __align__(256) int   g_cursor[E_];
__device__ __align__(256) int   g_aoff[E_ + 1];
__device__ __align__(256) int   g_tile_expert[NT];
__device__ __align__(256) int   g_assign_token[RP];
__device__ __align__(256) float g_assign_w[RP];
__device__ __align__(256) int   g_token_slot[2 * T_];

__device__ __align__(256) __half g_xh[T_ * D_];
__device__ __align__(256) __half g_xl[T_ * D_];
__device__ __align__(256) __half g_w1h[E_ * H_ * D_];  // W1^T: [E][H][D] K-major
__device__ __align__(256) __half g_w1l[E_ * H_ * D_];
__device__ __align__(256) __half g_w2h[E_ * D_ * H_];  // W2^T: [E][D][H] K-major
__device__ __align__(256) __half g_w2l[E_ * D_ * H_];
__device__ __align__(256) __half g_hh[RP * H_];        // h in fp16 (single plane)
__device__ __align__(256) float g_y[(size_t)RP * D_];

// ---------------- PTX helpers (baseline PTX only) ----------------
__device__ __forceinline__ uint32_t smem_u32(const void* p) {
    return (uint32_t)__cvta_generic_to_shared(p);
}
__device__ __forceinline__ void cpa16(uint32_t s, const void* g) {
    asm volatile("cp.async.cg.shared.global [%0], [%1], 16;\n" :: "r"(s), "l"(g));
}
__device__ __forceinline__ void cpa_commit() {
    asm volatile("cp.async.commit_group;\n" ::: "memory");
}
__device__ __forceinline__ void mma_f16(float* d, const uint32_t* a, const uint32_t* b) {
    asm volatile(
        "mma.sync.aligned.m16n8k16.row.col.f32.f16.f16.f32 "
        "{%0,%1,%2,%3}, {%4,%5,%6,%7}, {%8,%9}, {%0,%1,%2,%3};"
        : "+f"(d[0]), "+f"(d[1]), "+f"(d[2]), "+f"(d[3])
        : "r"(a[0]), "r"(a[1]), "r"(a[2]), "r"(a[3]), "r"(b[0]), "r"(b[1]));
}

// ---------------- reset ----------------
__global__ void k_reset() {
    int i = blockIdx.x * blockDim.x + threadIdx.x;
    if (i < RP) { g_assign_token[i] = -1; g_assign_w[i] = 0.f; }
    if (i < E_) g_cnt[i] = 0;
}

// ---------------- router ----------------
__global__ void k_router(const float* __restrict__ x, const float* __restrict__ Wg) {
    int t = blockIdx.x;
    int lane = threadIdx.x & 31, w = threadIdx.x >> 5;
    const float* xt = x + (size_t)t * D_;
    const float* wg = Wg + (size_t)w * D_;
    float s = 0.f;
    #pragma unroll 8
    for (int j = lane; j < D_; j += 32) s += xt[j] * wg[j];
    #pragma unroll
    for (int o = 16; o; o >>= 1) s += __shfl_xor_sync(0xffffffffu, s, o);
    __shared__ float sl[E_];
    if (lane == 0) sl[w] = s;
    __syncthreads();
    if (threadIdx.x == 0) {
        float mx = sl[0];
        #pragma unroll
        for (int e = 1; e < E_; e++) mx = fmaxf(mx, sl[e]);
        float p[E_], sum = 0.f;
        #pragma unroll
        for (int e = 0; e < E_; e++) { p[e] = __expf(sl[e] - mx); sum += p[e]; }
        float inv = 1.f / sum;
        #pragma unroll
        for (int e = 0; e < E_; e++) { p[e] *= inv; g_probs[t * E_ + e] = p[e]; }
        int i0 = 0;
        #pragma unroll
        for (int e = 1; e < E_; e++) if (p[e] > p[i0]) i0 = e;
        int i1 = -1;
        #pragma unroll
        for (int e = 0; e < E_; e++) {
            if (e == i0) continue;
            if (i1 < 0 || p[e] > p[i1]) i1 = e;
        }
        float v0 = p[i0], v1 = p[i1], s2 = v0 + v1;
        g_top_i[2 * t] = i0;  g_top_i[2 * t + 1] = i1;
        g_top_w[2 * t] = v0 / s2;  g_top_w[2 * t + 1] = v1 / s2;
        atomicAdd(&g_cnt[i0], 1);
        atomicAdd(&g_cnt[i1], 1);
    }
}

__global__ void k_probs_reduce() {
    int e = blockIdx.x, tid = threadIdx.x;
    float s = 0.f;
    for (int t = tid; t < T_; t += 256) s += g_probs[t * E_ + e];
    __shared__ float red[256];
    red[tid] = s; __syncthreads();
    for (int o = 128; o; o >>= 1) { if (tid < o) red[tid] += red[tid + o]; __syncthreads(); }
    if (tid == 0) g_probsum[e] = red[0];
}

__global__ void k_plan() {
    if (threadIdx.x == 0) {
        int off = 0;
        for (int e = 0; e < E_; e++) {
            g_aoff[e] = off;
            int c = g_cnt[e];
            int tiles = (c + TM - 1) / TM;
            int bt = off / TM;
            for (int tt = 0; tt < tiles; tt++) g_tile_expert[bt + tt] = e;
            off += tiles * TM;
            g_cursor[e] = 0;
        }
        g_aoff[E_] = off;
        for (int m = off / TM; m < NT; m++) g_tile_expert[m] = -1;
    }
}

__global__ void k_scatter() {
    int t = blockIdx.x * blockDim.x + threadIdx.x;
    if (t >= T_) return;
    #pragma unroll
    for (int k = 0; k < TOPK; k++) {
        int e = g_top_i[2 * t + k];
        int pos = atomicAdd(&g_cursor[e], 1);
        int slot = g_aoff[e] + pos;
        g_assign_token[slot] = t;
        g_assign_w[slot] = g_top_w[2 * t + k];
        g_token_slot[2 * t + k] = slot;
    }
}

// ---------------- prep: fp32 -> fp16 hi/lo planes ----------------
__global__ void k_cvt_x(const float* __restrict__ x) {
    int i = blockIdx.x * 256 + threadIdx.x;
    if (i < T_ * D_) {
        float v = x[i];
        __half h = __float2half(v);
        g_xh[i] = h;
        g_xl[i] = __float2half(v - __half2float(h));
    }
}

// transpose + split: W [E][R][Cc] -> global planes [E][Cc][R] (fp16 hi/lo).
// Destination __device__ symbols selected INSIDE device code (host-shadow trap).
template<bool W1SEL>
__global__ void k_tr(const float* __restrict__ W) {
    constexpr int R  = W1SEL ? D_ : H_;   // contraction dim
    constexpr int Cc = W1SEL ? H_ : D_;   // output-major dim
    __half* Oh = W1SEL ? g_w1h : g_w2h;
    __half* Ol = W1SEL ? g_w1l : g_w2l;
    __shared__ float t[32][33];
    int ez = blockIdx.z;
    const float* We = W + (size_t)ez * R * Cc;
    int c0 = blockIdx.x * 32, r0 = blockIdx.y * 32;
    int tx = threadIdx.x, ty = threadIdx.y;
    #pragma unroll
    for (int i = ty; i < 32; i += 8)
        t[i][tx] = We[(size_t)(r0 + i) * Cc + c0 + tx];
    __syncthreads();
    __half* OhE = Oh + (size_t)ez * R * Cc;
    __half* OlE = Ol + (size_t)ez * R * Cc;
    #pragma unroll
    for (int i = ty; i < 32; i += 8) {
        float v = t[tx][i];
        __half h = __float2half(v);
        size_t o = (size_t)(c0 + i) * R + r0 + tx;
        OhE[o] = h;
        OlE[o] = __float2half(v - __half2float(h));
    }
}

// ---------------- grouped GEMM via mma.sync (fp16 split) ----------------
// G1: 3 passes (Ah.Bh + Al.Bh + Ah.Bl), A = x hi/lo.   h -> single fp16 plane.
// G2: 2 passes (A.Bh + A.Bl), A = h fp16.
// CTA 128x128, KC=32 double-buffered cp.async, 8 warps of 32x64, direct-LDS frags.
template<bool G1>
__global__ __launch_bounds__(256) void k_gemm_mma(const float* __restrict__ bias_all) {
    int mt = blockIdx.y, nb = blockIdx.x;
    int e = g_tile_expert[mt];
    if (e < 0) return;
    extern __shared__ char smem[];
    float* s_bias = (float*)smem;
    int*   s_tok  = (int*)(smem + 512);
    char*  sdata  = smem + 1024;
    uint32_t sb32 = smem_u32(smem) + 1024;
    constexpr int KD  = G1 ? D_ : H_;
    constexpr int NBW = G1 ? H_ : D_;
    constexpr int C   = KD / KC;
    constexpr int NA  = G1 ? 2 : 1;            // A planes
    constexpr int STG_T = (NA + 2) * PL;       // stage bytes
    int tid = threadIdx.x, lane = tid & 31, wid = tid >> 5;
    int row0 = mt * TM;

    if (tid < 128) s_bias[tid] = bias_all[(size_t)e * NBW + nb * 128 + tid];
    if (G1 && tid < 128) { int tk = g_assign_token[row0 + tid]; s_tok[tid] = tk < 0 ? 0 : tk; }
    __syncthreads();

    const __half *Ah, *Al, *Bh, *Bl;
    if (G1) { Ah = g_xh; Al = g_xl; Bh = g_w1h; Bl = g_w1l; }
    else    { Ah = g_hh; Al = nullptr; Bh = g_w2h; Bl = g_w2l; }
    size_t bbase = (size_t)e * (size_t)H_ * D_ + (size_t)(nb * 128) * KD;

    auto load_chunk = [&](int c, int s) {
        uint32_t st = sb32 + s * STG_T;
        int k0 = c * KC;
        #pragma unroll
        for (int q = tid; q < 512; q += 256) {           // A plane(s): 128 rows x 64B
            int r = q >> 2, cc = q & 3;
            size_t go = (G1 ? (size_t)s_tok[r] * D_ : (size_t)(row0 + r) * H_) + k0 + cc * 8;
            uint32_t so = (uint32_t)(r * RSB + cc * 16);
            cpa16(st + so, Ah + go);
            if (G1) cpa16(st + PL + so, Al + go);
        }
        #pragma unroll
        for (int q = tid; q < 512; q += 256) {           // B hi/lo: 128 rows x 64B
            int r = q >> 2, cc = q & 3;
            size_t go = bbase + (size_t)r * KD + k0 + cc * 8;
            uint32_t so = (uint32_t)(r * RSB + cc * 16);
            cpa16(st + NA * PL + so, Bh + go);
            cpa16(st + (NA + 1) * PL + so, Bl + go);
        }
        cpa_commit();
    };

    int wm = (wid & 3) * 32, wn = (wid >> 2) * 64;
    int g = lane >> 2, tig = lane & 3;
    uint32_t aF = (uint32_t)((wm + g) * RSB + tig * 4);
    uint32_t bF = (uint32_t)((wn + g) * RSB + tig * 4);

    float acc[2][8][4] = {};
    load_chunk(0, 0);
    for (int c = 0; c < C; ++c) {
        int s = c & 1;
        if (c + 1 < C) {
            load_chunk(c + 1, s ^ 1);
            asm volatile("cp.async.wait_group 1;\n" ::: "memory");
        } else {
            asm volatile("cp.async.wait_group 0;\n" ::: "memory");
        }
        __syncthreads();
        char* pAh = sdata + s * STG_T;
        char* pAl = pAh + PL;                 // valid only if G1
        char* pBh = pAh + NA * PL;
        char* pBl = pBh + PL;
        #pragma unroll
        for (int ks = 0; ks < 2; ks++) {
            uint32_t ko = ks * 32;
            uint32_t am[8], bx[16];
            #pragma unroll
            for (int m = 0; m < 2; m++) {
                uint32_t base = aF + m * 16 * RSB + ko;
                am[4 * m + 0] = *(const uint32_t*)(pAh + base);
                am[4 * m + 1] = *(const uint32_t*)(pAh + base + 8 * RSB);
                am[4 * m + 2] = *(const uint32_t*)(pAh + base + 16);
                am[4 * m + 3] = *(const uint32_t*)(pAh + base + 8 * RSB + 16);
            }
            #pragma unroll
            for (int n = 0; n < 8; n++) {
                uint32_t base = bF + n * 8 * RSB + ko;
                bx[2 * n + 0] = *(const uint32_t*)(pBh + base);
                bx[2 * n + 1] = *(const uint32_t*)(pBh + base + 16);
            }
            #pragma unroll
            for (int m = 0; m < 2; m++)
                #pragma unroll
                for (int n = 0; n < 8; n++)
                    mma_f16(acc[m][n], am + 4 * m, bx + 2 * n);      // hi*hi
            if (G1) {   // lo(A) * hi(B)
                uint32_t al[8];
                #pragma unroll
                for (int m = 0; m < 2; m++) {
                    uint32_t base = aF + m * 16 * RSB + ko;
                    al[4 * m + 0] = *(const uint32_t*)(pAl + base);
                    al[4 * m + 1] = *(const uint32_t*)(pAl + base + 8 * RSB);
                    al[4 * m + 2] = *(const uint32_t*)(pAl + base + 16);
                    al[4 * m + 3] = *(const uint32_t*)(pAl + base + 8 * RSB + 16);
                }
                #pragma unroll
                for (int m = 0; m < 2; m++)
                    #pragma unroll
                    for (int n = 0; n < 8; n++)
                        mma_f16(acc[m][n], al + 4 * m, bx + 2 * n);
            }
            {   // hi(A) * lo(B)
                #pragma unroll
                for (int n = 0; n < 8; n++) {
                    uint32_t base = bF + n * 8 * RSB + ko;
                    bx[2 * n + 0] = *(const uint32_t*)(pBl + base);
                    bx[2 * n + 1] = *(const uint32_t*)(pBl + base + 16);
                }
                #pragma unroll
                for (int m = 0; m < 2; m++)
                    #pragma unroll
                    for (int n = 0; n < 8; n++)
                        mma_f16(acc[m][n], am + 4 * m, bx + 2 * n);
            }
        }
        __syncthreads();
    }

    // ---- epilogue ----
    int rbase = row0 + wm + g;
    int cloc0 = wn + tig * 2;
    #pragma unroll
    for (int m = 0; m < 2; m++) {
        #pragma unroll
        for (int n = 0; n < 8; n++) {
            int cl = cloc0 + n * 8;
            int gc = nb * 128 + cl;
            float b0 = s_bias[cl], b1 = s_bias[cl + 1];
            #pragma unroll
            for (int hrow = 0; hrow < 2; hrow++) {
                int gr = rbase + m * 16 + hrow * 8;
                float v0 = acc[m][n][2 * hrow + 0] + b0;
                float v1 = acc[m][n][2 * hrow + 1] + b1;
                if (G1) {
                    float s0 = v0 * __fdividef(1.f, 1.f + __expf(-v0));
                    float s1 = v1 * __fdividef(1.f, 1.f + __expf(-v1));
                    __half2 hp; hp.x = __float2half(s0); hp.y = __float2half(s1);
                    *(__half2*)(g_hh + (size_t)gr * H_ + gc) = hp;
                } else {
                    size_t o = (size_t)gr * D_ + gc;
                    float2 fv; fv.x = v0; fv.y = v1;
                    *(float2*)(g_y + o) = fv;
                }
            }
        }
    }
}

// ---------------- combine + aux ----------------
__global__ void k_combine(float* __restrict__ out) {
    int idx = blockIdx.x * 256 + threadIdx.x;
    if (idx >= T_ * D_ / 4) return;
    int t = idx / (D_ / 4);
    int v = idx % (D_ / 4);
    int s0 = g_token_slot[2 * t], s1 = g_token_slot[2 * t + 1];
    float w0 = g_assign_w[s0], w1 = g_assign_w[s1];
    float4 y0 = *(const float4*)(g_y + (size_t)s0 * D_ + v * 4);
    float4 y1 = *(const float4*)(g_y + (size_t)s1 * D_ + v * 4);
    float4 o;
    o.x = w0 * y0.x + w1 * y1.x;
    o.y = w0 * y0.y + w1 * y1.y;
    o.z = w0 * y0.z + w1 * y1.z;
    o.w = w0 * y0.w + w1 * y1.w;
    *(float4*)(out + (size_t)t * D_ + v * 4) = o;
}

__global__ void k_aux(float* __restrict__ out, int out_size) {
    if (threadIdx.x == 0 && out_size > T_ * D_) {
        float a = 0.f;
        #pragma unroll
        for (int e = 0; e < E_; e++)
            a += ((float)g_cnt[e] / (float)T_) * (g_probsum[e] / (float)T_);
        out[(size_t)T_ * D_] = (float)E_ * a;
    }
}

// ---------------- launch ----------------
extern "C" void kernel_launch(void* const* d_in, const int* in_sizes, int n_in,
                              void* d_out, int out_size) {
    const float* x  = (const float*)d_in[0];
    const float* Wg = (const float*)d_in[1];
    const float* W1 = (const float*)d_in[2];
    const float* b1 = (const float*)d_in[3];
    const float* W2 = (const float*)d_in[4];
    const float* b2 = (const float*)d_in[5];
    float* out = (float*)d_out;
    (void)in_sizes; (void)n_in;

    cudaFuncSetAttribute(k_gemm_mma<true>,
                         cudaFuncAttributeMaxDynamicSharedMemorySize, SMEM1);
    cudaFuncSetAttribute(k_gemm_mma<false>,
                         cudaFuncAttributeMaxDynamicSharedMemorySize, SMEM2);

    k_reset<<<(RP + 255) / 256, 256>>>();
    k_router<<<T_, 256>>>(x, Wg);
    k_probs_reduce<<<E_, 256>>>();
    k_plan<<<1, 32>>>();
    k_scatter<<<(T_ + 255) / 256, 256>>>();

    // prep: fp32 -> fp16 hi/lo planes, weights transposed K-major
    k_cvt_x<<<(T_ * D_ + 255) / 256, 256>>>(x);
    k_tr<true ><<<dim3(H_ / 32, D_ / 32, E_), dim3(32, 8)>>>(W1);
    k_tr<false><<<dim3(D_ / 32, H_ / 32, E_), dim3(32, 8)>>>(W2);

    k_gemm_mma<true ><<<dim3(H_ / 128, NT), 256, SMEM1>>>(b1);
    k_gemm_mma<false><<<dim3(D_ / 128, NT), 256, SMEM2>>>(b2);

    k_combine<<<(T_ * D_ / 4 + 255) / 256, 256>>>(out);
    k_aux<<<1, 32>>>(out, out_size);
}

// round 14
// speedup vs baseline: 4.3909x; 1.7192x over previous
#include <cuda_runtime.h>
#include <cuda_fp16.h>
#include <cstdint>

// ---------------- problem constants ----------------
constexpr int T_  = 4096;
constexpr int D_  = 1024;
constexpr int H_  = 4096;
constexpr int E_  = 8;
constexpr int TOPK = 2;

constexpr int TM = 128;
constexpr int RP = 9216;
constexpr int NT = RP / TM;      // 72 row tiles

// mma GEMM tiling
constexpr int KC  = 32;          // K elems per chunk
constexpr int RSB = 80;          // smem row stride bytes (64B data + 16B pad)
constexpr int PL  = 128 * RSB;   // 10240 B per plane (128 rows)
constexpr int SMEM_G = 1024 + 2 * 2 * PL;   // A,B x 2 stages = 41984 B

// ---------------- device-global scratch (256B-aligned: cp.async-safe) ----
__device__ __align__(256) int   g_top_i[2 * T_];
__device__ __align__(256) float g_top_w[2 * T_];
__device__ __align__(256) float g_probs[T_ * E_];
__device__ __align__(256) float g_probsum[E_];
__device__ __align__(256) int   g_cnt[E_];
__device__ __align__(256) int   g_cursor[E_];
__device__ __align__(256) int   g_aoff[E_ + 1];
__device__ __align__(256) int   g_tile_expert[NT];
__device__ __align__(256) int   g_assign_token[RP];
__device__ __align__(256) float g_assign_w[RP];
__device__ __align__(256) int   g_token_slot[2 * T_];

__device__ __align__(256) __half g_x16[T_ * D_];
__device__ __align__(256) __half g_w1[E_ * H_ * D_];  // W1^T: [E][H][D] K-major
__device__ __align__(256) __half g_w2[E_ * D_ * H_];  // W2^T: [E][D][H] K-major
__device__ __align__(256) __half g_hh[RP * H_];       // h in fp16
__device__ __align__(256) float g_y[(size_t)RP * D_];

// ---------------- PTX helpers (baseline PTX only) ----------------
__device__ __forceinline__ uint32_t smem_u32(const void* p) {
    return (uint32_t)__cvta_generic_to_shared(p);
}
__device__ __forceinline__ void cpa16(uint32_t s, const void* g) {
    asm volatile("cp.async.cg.shared.global [%0], [%1], 16;\n" :: "r"(s), "l"(g));
}
__device__ __forceinline__ void cpa_commit() {
    asm volatile("cp.async.commit_group;\n" ::: "memory");
}
__device__ __forceinline__ void mma_f16(float* d, const uint32_t* a, const uint32_t* b) {
    asm volatile(
        "mma.sync.aligned.m16n8k16.row.col.f32.f16.f16.f32 "
        "{%0,%1,%2,%3}, {%4,%5,%6,%7}, {%8,%9}, {%0,%1,%2,%3};"
        : "+f"(d[0]), "+f"(d[1]), "+f"(d[2]), "+f"(d[3])
        : "r"(a[0]), "r"(a[1]), "r"(a[2]), "r"(a[3]), "r"(b[0]), "r"(b[1]));
}

// ---------------- reset ----------------
__global__ void k_reset() {
    int i = blockIdx.x * blockDim.x + threadIdx.x;
    if (i < RP) { g_assign_token[i] = -1; g_assign_w[i] = 0.f; }
    if (i < E_) g_cnt[i] = 0;
}

// ---------------- router ----------------
__global__ void k_router(const float* __restrict__ x, const float* __restrict__ Wg) {
    int t = blockIdx.x;
    int lane = threadIdx.x & 31, w = threadIdx.x >> 5;
    const float* xt = x + (size_t)t * D_;
    const float* wg = Wg + (size_t)w * D_;
    float s = 0.f;
    #pragma unroll 8
    for (int j = lane; j < D_; j += 32) s += xt[j] * wg[j];
    #pragma unroll
    for (int o = 16; o; o >>= 1) s += __shfl_xor_sync(0xffffffffu, s, o);
    __shared__ float sl[E_];
    if (lane == 0) sl[w] = s;
    __syncthreads();
    if (threadIdx.x == 0) {
        float mx = sl[0];
        #pragma unroll
        for (int e = 1; e < E_; e++) mx = fmaxf(mx, sl[e]);
        float p[E_], sum = 0.f;
        #pragma unroll
        for (int e = 0; e < E_; e++) { p[e] = __expf(sl[e] - mx); sum += p[e]; }
        float inv = 1.f / sum;
        #pragma unroll
        for (int e = 0; e < E_; e++) { p[e] *= inv; g_probs[t * E_ + e] = p[e]; }
        int i0 = 0;
        #pragma unroll
        for (int e = 1; e < E_; e++) if (p[e] > p[i0]) i0 = e;
        int i1 = -1;
        #pragma unroll
        for (int e = 0; e < E_; e++) {
            if (e == i0) continue;
            if (i1 < 0 || p[e] > p[i1]) i1 = e;
        }
        float v0 = p[i0], v1 = p[i1], s2 = v0 + v1;
        g_top_i[2 * t] = i0;  g_top_i[2 * t + 1] = i1;
        g_top_w[2 * t] = v0 / s2;  g_top_w[2 * t + 1] = v1 / s2;
        atomicAdd(&g_cnt[i0], 1);
        atomicAdd(&g_cnt[i1], 1);
    }
}

__global__ void k_probs_reduce() {
    int e = blockIdx.x, tid = threadIdx.x;
    float s = 0.f;
    for (int t = tid; t < T_; t += 256) s += g_probs[t * E_ + e];
    __shared__ float red[256];
    red[tid] = s; __syncthreads();
    for (int o = 128; o; o >>= 1) { if (tid < o) red[tid] += red[tid + o]; __syncthreads(); }
    if (tid == 0) g_probsum[e] = red[0];
}

__global__ void k_plan() {
    if (threadIdx.x == 0) {
        int off = 0;
        for (int e = 0; e < E_; e++) {
            g_aoff[e] = off;
            int c = g_cnt[e];
            int tiles = (c + TM - 1) / TM;
            int bt = off / TM;
            for (int tt = 0; tt < tiles; tt++) g_tile_expert[bt + tt] = e;
            off += tiles * TM;
            g_cursor[e] = 0;
        }
        g_aoff[E_] = off;
        for (int m = off / TM; m < NT; m++) g_tile_expert[m] = -1;
    }
}

__global__ void k_scatter() {
    int t = blockIdx.x * blockDim.x + threadIdx.x;
    if (t >= T_) return;
    #pragma unroll
    for (int k = 0; k < TOPK; k++) {
        int e = g_top_i[2 * t + k];
        int pos = atomicAdd(&g_cursor[e], 1);
        int slot = g_aoff[e] + pos;
        g_assign_token[slot] = t;
        g_assign_w[slot] = g_top_w[2 * t + k];
        g_token_slot[2 * t + k] = slot;
    }
}

// ---------------- prep: fp32 -> fp16 ----------------
__global__ void k_cvt_x(const float* __restrict__ x) {
    int i = blockIdx.x * 256 + threadIdx.x;
    if (i < T_ * D_) g_x16[i] = __float2half(x[i]);
}

// transpose: W [E][R][Cc] -> global plane [E][Cc][R] fp16.
// Destination __device__ symbol selected INSIDE device code (host-shadow trap).
template<bool W1SEL>
__global__ void k_tr(const float* __restrict__ W) {
    constexpr int R  = W1SEL ? D_ : H_;   // contraction dim
    constexpr int Cc = W1SEL ? H_ : D_;   // output-major dim
    __half* Oh = W1SEL ? g_w1 : g_w2;
    __shared__ float t[32][33];
    int ez = blockIdx.z;
    const float* We = W + (size_t)ez * R * Cc;
    int c0 = blockIdx.x * 32, r0 = blockIdx.y * 32;
    int tx = threadIdx.x, ty = threadIdx.y;
    #pragma unroll
    for (int i = ty; i < 32; i += 8)
        t[i][tx] = We[(size_t)(r0 + i) * Cc + c0 + tx];
    __syncthreads();
    __half* OhE = Oh + (size_t)ez * R * Cc;
    #pragma unroll
    for (int i = ty; i < 32; i += 8)
        OhE[(size_t)(c0 + i) * R + r0 + tx] = __float2half(t[tx][i]);
}

// ---------------- grouped GEMM via mma.sync (pure fp16) ----------------
// CTA 128x128, KC=32 double-buffered cp.async, 8 warps of 32x64, direct-LDS frags.
template<bool G1>
__global__ __launch_bounds__(256) void k_gemm_mma(const float* __restrict__ bias_all) {
    int mt = blockIdx.y, nb = blockIdx.x;
    int e = g_tile_expert[mt];
    if (e < 0) return;
    extern __shared__ char smem[];
    float* s_bias = (float*)smem;
    int*   s_tok  = (int*)(smem + 512);
    char*  sdata  = smem + 1024;
    uint32_t sb32 = smem_u32(smem) + 1024;
    constexpr int KD  = G1 ? D_ : H_;
    constexpr int NBW = G1 ? H_ : D_;
    constexpr int C   = KD / KC;
    constexpr int STG_T = 2 * PL;              // A + B per stage
    int tid = threadIdx.x, lane = tid & 31, wid = tid >> 5;
    int row0 = mt * TM;

    if (tid < 128) s_bias[tid] = bias_all[(size_t)e * NBW + nb * 128 + tid];
    if (G1 && tid < 128) { int tk = g_assign_token[row0 + tid]; s_tok[tid] = tk < 0 ? 0 : tk; }
    __syncthreads();

    const __half* A = G1 ? g_x16 : g_hh;
    const __half* B = G1 ? g_w1  : g_w2;
    size_t bbase = (size_t)e * (size_t)H_ * D_ + (size_t)(nb * 128) * KD;

    auto load_chunk = [&](int c, int s) {
        uint32_t st = sb32 + s * STG_T;
        int k0 = c * KC;
        #pragma unroll
        for (int q = tid; q < 512; q += 256) {           // A: 128 rows x 64B
            int r = q >> 2, cc = q & 3;
            size_t go = (G1 ? (size_t)s_tok[r] * D_ : (size_t)(row0 + r) * H_) + k0 + cc * 8;
            cpa16(st + (uint32_t)(r * RSB + cc * 16), A + go);
        }
        #pragma unroll
        for (int q = tid; q < 512; q += 256) {           // B: 128 rows x 64B
            int r = q >> 2, cc = q & 3;
            size_t go = bbase + (size_t)r * KD + k0 + cc * 8;
            cpa16(st + PL + (uint32_t)(r * RSB + cc * 16), B + go);
        }
        cpa_commit();
    };

    int wm = (wid & 3) * 32, wn = (wid >> 2) * 64;
    int g = lane >> 2, tig = lane & 3;
    uint32_t aF = (uint32_t)((wm + g) * RSB + tig * 4);
    uint32_t bF = (uint32_t)((wn + g) * RSB + tig * 4);

    float acc[2][8][4] = {};
    load_chunk(0, 0);
    for (int c = 0; c < C; ++c) {
        int s = c & 1;
        if (c + 1 < C) {
            load_chunk(c + 1, s ^ 1);
            asm volatile("cp.async.wait_group 1;\n" ::: "memory");
        } else {
            asm volatile("cp.async.wait_group 0;\n" ::: "memory");
        }
        __syncthreads();
        char* pA = sdata + s * STG_T;
        char* pB = pA + PL;
        #pragma unroll
        for (int ks = 0; ks < 2; ks++) {
            uint32_t ko = ks * 32;
            uint32_t am[8], bx[16];
            #pragma unroll
            for (int m = 0; m < 2; m++) {
                uint32_t base = aF + m * 16 * RSB + ko;
                am[4 * m + 0] = *(const uint32_t*)(pA + base);
                am[4 * m + 1] = *(const uint32_t*)(pA + base + 8 * RSB);
                am[4 * m + 2] = *(const uint32_t*)(pA + base + 16);
                am[4 * m + 3] = *(const uint32_t*)(pA + base + 8 * RSB + 16);
            }
            #pragma unroll
            for (int n = 0; n < 8; n++) {
                uint32_t base = bF + n * 8 * RSB + ko;
                bx[2 * n + 0] = *(const uint32_t*)(pB + base);
                bx[2 * n + 1] = *(const uint32_t*)(pB + base + 16);
            }
            #pragma unroll
            for (int m = 0; m < 2; m++)
                #pragma unroll
                for (int n = 0; n < 8; n++)
                    mma_f16(acc[m][n], am + 4 * m, bx + 2 * n);
        }
        __syncthreads();
    }

    // ---- epilogue ----
    int rbase = row0 + wm + g;
    int cloc0 = wn + tig * 2;
    #pragma unroll
    for (int m = 0; m < 2; m++) {
        #pragma unroll
        for (int n = 0; n < 8; n++) {
            int cl = cloc0 + n * 8;
            int gc = nb * 128 + cl;
            float b0 = s_bias[cl], b1 = s_bias[cl + 1];
            #pragma unroll
            for (int hrow = 0; hrow < 2; hrow++) {
                int gr = rbase + m * 16 + hrow * 8;
                float v0 = acc[m][n][2 * hrow + 0] + b0;
                float v1 = acc[m][n][2 * hrow + 1] + b1;
                if (G1) {
                    float s0 = v0 * __fdividef(1.f, 1.f + __expf(-v0));
                    float s1 = v1 * __fdividef(1.f, 1.f + __expf(-v1));
                    __half2 hp; hp.x = __float2half(s0); hp.y = __float2half(s1);
                    *(__half2*)(g_hh + (size_t)gr * H_ + gc) = hp;
                } else {
                    size_t o = (size_t)gr * D_ + gc;
                    float2 fv; fv.x = v0; fv.y = v1;
                    *(float2*)(g_y + o) = fv;
                }
            }
        }
    }
}

// ---------------- combine + aux ----------------
__global__ void k_combine(float* __restrict__ out) {
    int idx = blockIdx.x * 256 + threadIdx.x;
    if (idx >= T_ * D_ / 4) return;
    int t = idx / (D_ / 4);
    int v = idx % (D_ / 4);
    int s0 = g_token_slot[2 * t], s1 = g_token_slot[2 * t + 1];
    float w0 = g_assign_w[s0], w1 = g_assign_w[s1];
    float4 y0 = *(const float4*)(g_y + (size_t)s0 * D_ + v * 4);
    float4 y1 = *(const float4*)(g_y + (size_t)s1 * D_ + v * 4);
    float4 o;
    o.x = w0 * y0.x + w1 * y1.x;
    o.y = w0 * y0.y + w1 * y1.y;
    o.z = w0 * y0.z + w1 * y1.z;
    o.w = w0 * y0.w + w1 * y1.w;
    *(float4*)(out + (size_t)t * D_ + v * 4) = o;
}

__global__ void k_aux(float* __restrict__ out, int out_size) {
    if (threadIdx.x == 0 && out_size > T_ * D_) {
        float a = 0.f;
        #pragma unroll
        for (int e = 0; e < E_; e++)
            a += ((float)g_cnt[e] / (float)T_) * (g_probsum[e] / (float)T_);
        out[(size_t)T_ * D_] = (float)E_ * a;
    }
}

// ---------------- launch ----------------
extern "C" void kernel_launch(void* const* d_in, const int* in_sizes, int n_in,
                              void* d_out, int out_size) {
    const float* x  = (const float*)d_in[0];
    const float* Wg = (const float*)d_in[1];
    const float* W1 = (const float*)d_in[2];
    const float* b1 = (const float*)d_in[3];
    const float* W2 = (const float*)d_in[4];
    const float* b2 = (const float*)d_in[5];
    float* out = (float*)d_out;
    (void)in_sizes; (void)n_in;

    cudaFuncSetAttribute(k_gemm_mma<true>,
                         cudaFuncAttributeMaxDynamicSharedMemorySize, SMEM_G);
    cudaFuncSetAttribute(k_gemm_mma<false>,
                         cudaFuncAttributeMaxDynamicSharedMemorySize, SMEM_G);

    k_reset<<<(RP + 255) / 256, 256>>>();
    k_router<<<T_, 256>>>(x, Wg);
    k_probs_reduce<<<E_, 256>>>();
    k_plan<<<1, 32>>>();
    k_scatter<<<(T_ + 255) / 256, 256>>>();

    // prep: fp32 -> fp16, weights transposed K-major
    k_cvt_x<<<(T_ * D_ + 255) / 256, 256>>>(x);
    k_tr<true ><<<dim3(H_ / 32, D_ / 32, E_), dim3(32, 8)>>>(W1);
    k_tr<false><<<dim3(D_ / 32, H_ / 32, E_), dim3(32, 8)>>>(W2);

    k_gemm_mma<true ><<<dim3(H_ / 128, NT), 256, SMEM_G>>>(b1);
    k_gemm_mma<false><<<dim3(D_ / 128, NT), 256, SMEM_G>>>(b2);

    k_combine<<<(T_ * D_ / 4 + 255) / 256, 256>>>(out);
    k_aux<<<1, 32>>>(out, out_size);
}